// round 1
// baseline (speedup 1.0000x reference)
#include <cuda_runtime.h>
#include <cuda_bf16.h>
#include <math.h>

// Problem constants
#define BB 2
#define SS 2048
#define DD 1024
#define HH 16
#define HDIM 64
#define II 3752
#define MROWS (BB*SS)          // 4096
#define EPS 1e-6f

// ---------------- scratch (device globals; no allocation at runtime) ----------------
__device__ float g_h   [MROWS * DD];
__device__ float g_q   [MROWS * DD];
__device__ float g_k   [MROWS * DD];
__device__ float g_v   [MROWS * DD];
__device__ float g_att [MROWS * DD];
__device__ float g_res1[MROWS * DD];
__device__ float g_h2  [MROWS * DD];
__device__ float g_gate[MROWS * II];
__device__ float g_up  [MROWS * II];

// ---------------- RMSNorm ----------------
__global__ void rmsnorm_kernel(const float* __restrict__ x, const float* __restrict__ w,
                               float* __restrict__ out)
{
    int row = blockIdx.x;
    const float* xr = x + (size_t)row * DD;
    float sum = 0.f;
    for (int c = threadIdx.x; c < DD; c += 256) { float t = xr[c]; sum += t * t; }
    __shared__ float red[256];
    red[threadIdx.x] = sum;
    __syncthreads();
    for (int s = 128; s > 0; s >>= 1) {
        if (threadIdx.x < s) red[threadIdx.x] += red[threadIdx.x + s];
        __syncthreads();
    }
    float r = rsqrtf(red[0] * (1.0f / DD) + EPS);
    float* orow = out + (size_t)row * DD;
    for (int c = threadIdx.x; c < DD; c += 256) orow[c] = w[c] * (xr[c] * r);
}

// ---------------- tiled fp32 GEMM: C[M,N] = A[M,K] @ W[K,N] (+bias) (+residual) ----------------
#define BM 64
#define BN 64
#define BK 16

__global__ __launch_bounds__(256) void gemm_kernel(
    const float* __restrict__ A, const float* __restrict__ W,
    const float* __restrict__ bias, const float* __restrict__ res,
    float* __restrict__ C, int M, int N, int K)
{
    __shared__ float As[BK][BM];
    __shared__ float Bs[BK][BN];

    int tid = threadIdx.x;
    int tx = tid & 15;          // 0..15 -> col group
    int ty = tid >> 4;          // 0..15 -> row group
    int bm = blockIdx.y * BM;
    int bn = blockIdx.x * BN;

    float acc[4][4] = {};

    for (int k0 = 0; k0 < K; k0 += BK) {
        // --- load A tile (BM x BK), transposed into As[k][m] ---
        {
            int r = tid >> 2;            // 0..63
            int c = (tid & 3) * 4;       // 0,4,8,12
            float4 a4 = make_float4(0.f, 0.f, 0.f, 0.f);
            if (bm + r < M && (k0 + c + 4) <= K)
                a4 = *(const float4*)&A[(size_t)(bm + r) * K + k0 + c];
            As[c + 0][r] = a4.x; As[c + 1][r] = a4.y;
            As[c + 2][r] = a4.z; As[c + 3][r] = a4.w;
        }
        // --- load B tile (BK x BN) ---
        {
            int r = tid >> 4;            // 0..15
            int c = (tid & 15) * 4;      // 0..60
            float4 b4 = make_float4(0.f, 0.f, 0.f, 0.f);
            if ((k0 + r) < K && (bn + c + 4) <= N)
                b4 = *(const float4*)&W[(size_t)(k0 + r) * N + bn + c];
            *(float4*)&Bs[r][c] = b4;
        }
        __syncthreads();

        #pragma unroll
        for (int kk = 0; kk < BK; kk++) {
            float4 a4 = *(const float4*)&As[kk][ty * 4];
            float4 b4 = *(const float4*)&Bs[kk][tx * 4];
            float a[4] = {a4.x, a4.y, a4.z, a4.w};
            float b[4] = {b4.x, b4.y, b4.z, b4.w};
            #pragma unroll
            for (int i = 0; i < 4; i++)
                #pragma unroll
                for (int j = 0; j < 4; j++)
                    acc[i][j] = fmaf(a[i], b[j], acc[i][j]);
        }
        __syncthreads();
    }

    // --- epilogue ---
    #pragma unroll
    for (int i = 0; i < 4; i++) {
        int row = bm + ty * 4 + i;
        if (row >= M) continue;
        #pragma unroll
        for (int j = 0; j < 4; j++) {
            int col = bn + tx * 4 + j;
            if (col >= N) continue;
            float v = acc[i][j];
            if (bias) v += bias[col];
            if (res)  v += res[(size_t)row * N + col];
            C[(size_t)row * N + col] = v;
        }
    }
}

// ---------------- attention: one block per (b, h, query-row) ----------------
// q,k,v,out layout: [B, S, H, HD] contiguous (== [B,S,D] after head merge)
__global__ __launch_bounds__(128) void attn_kernel(
    const float* __restrict__ q, const float* __restrict__ k, const float* __restrict__ v,
    const float* __restrict__ bias, float* __restrict__ out)
{
    const int i = blockIdx.x & (SS - 1);
    const int h = (blockIdx.x >> 11) & (HH - 1);
    const int b = blockIdx.x >> 15;
    const int tid = threadIdx.x;

    __shared__ float sq[HDIM];
    __shared__ float sc[SS];
    __shared__ float red[128];

    const float* qrow = q + ((size_t)(b * SS + i) * HH + h) * HDIM;
    if (tid < 16) *(float4*)&sq[tid * 4] = *(const float4*)&qrow[tid * 4];
    __syncthreads();

    const int nk = i + 1;   // causal
    const float* brow = bias + ((size_t)h * SS + i) * SS;

    float lmax = -INFINITY;
    for (int j = tid; j < nk; j += 128) {
        const float* krow = k + ((size_t)(b * SS + j) * HH + h) * HDIM;
        float dot = 0.f;
        #pragma unroll
        for (int d = 0; d < HDIM; d += 4) {
            float4 k4 = *(const float4*)&krow[d];
            dot = fmaf(sq[d + 0], k4.x, dot);
            dot = fmaf(sq[d + 1], k4.y, dot);
            dot = fmaf(sq[d + 2], k4.z, dot);
            dot = fmaf(sq[d + 3], k4.w, dot);
        }
        float s = dot * 0.125f + brow[j];    // HD^-0.5 = 1/8
        sc[j] = s;
        lmax = fmaxf(lmax, s);
    }
    red[tid] = lmax;
    __syncthreads();
    for (int s = 64; s > 0; s >>= 1) {
        if (tid < s) red[tid] = fmaxf(red[tid], red[tid + s]);
        __syncthreads();
    }
    float mx = red[0];
    __syncthreads();

    float lsum = 0.f;
    for (int j = tid; j < nk; j += 128) {
        float p = expf(sc[j] - mx);
        sc[j] = p;
        lsum += p;
    }
    red[tid] = lsum;
    __syncthreads();
    for (int s = 64; s > 0; s >>= 1) {
        if (tid < s) red[tid] += red[tid + s];
        __syncthreads();
    }
    float inv = 1.0f / red[0];
    __syncthreads();

    // out[d] = inv * sum_j p_j * v[j,d]; 2 partial threads per dim
    const int d = tid & 63;
    const int part = tid >> 6;
    float acc = 0.f;
    const float* vb = v + ((size_t)b * SS * HH + h) * HDIM;
    for (int j = part; j < nk; j += 2)
        acc = fmaf(sc[j], vb[(size_t)j * (HH * HDIM) + d], acc);
    red[tid] = acc;
    __syncthreads();
    if (tid < 64)
        out[((size_t)(b * SS + i) * HH + h) * HDIM + tid] = (red[tid] + red[tid + 64]) * inv;
}

// ---------------- SwiGLU elementwise: gate = silu(gate) * up ----------------
__global__ void swiglu_kernel(float* __restrict__ gate, const float* __restrict__ up, size_t n)
{
    size_t idx = (size_t)blockIdx.x * blockDim.x + threadIdx.x;
    if (idx < n) {
        float g = gate[idx];
        float s = g / (1.0f + expf(-g));
        gate[idx] = s * up[idx];
    }
}

// ---------------- launch ----------------
extern "C" void kernel_launch(void* const* d_in, const int* in_sizes, int n_in,
                              void* d_out, int out_size)
{
    const float* x      = (const float*)d_in[0];
    const float* wq     = (const float*)d_in[1];
    const float* bq     = (const float*)d_in[2];
    const float* wk     = (const float*)d_in[3];
    const float* bk     = (const float*)d_in[4];
    const float* wv     = (const float*)d_in[5];
    const float* bv     = (const float*)d_in[6];
    const float* wo     = (const float*)d_in[7];
    const float* bo     = (const float*)d_in[8];
    const float* w_gate = (const float*)d_in[9];
    const float* w_up   = (const float*)d_in[10];
    const float* w_down = (const float*)d_in[11];
    const float* ln1w   = (const float*)d_in[12];
    const float* ln2w   = (const float*)d_in[13];
    const float* abias  = (const float*)d_in[14];
    float* out = (float*)d_out;

    static float *pH = nullptr, *pQ, *pK, *pV, *pAtt, *pRes1, *pH2, *pGate, *pUp;
    if (!pH) {
        cudaGetSymbolAddress((void**)&pH,    g_h);
        cudaGetSymbolAddress((void**)&pQ,    g_q);
        cudaGetSymbolAddress((void**)&pK,    g_k);
        cudaGetSymbolAddress((void**)&pV,    g_v);
        cudaGetSymbolAddress((void**)&pAtt,  g_att);
        cudaGetSymbolAddress((void**)&pRes1, g_res1);
        cudaGetSymbolAddress((void**)&pH2,   g_h2);
        cudaGetSymbolAddress((void**)&pGate, g_gate);
        cudaGetSymbolAddress((void**)&pUp,   g_up);
    }

    dim3 gemmBlk(256);
    dim3 gD(DD / BN, MROWS / BM);                 // N=1024
    dim3 gI((II + BN - 1) / BN, MROWS / BM);      // N=3752

    // 1. h = rmsnorm(x, ln1_w)
    rmsnorm_kernel<<<MROWS, 256>>>(x, ln1w, pH);

    // 2. q,k,v projections
    gemm_kernel<<<gD, gemmBlk>>>(pH, wq, bq, nullptr, pQ, MROWS, DD, DD);
    gemm_kernel<<<gD, gemmBlk>>>(pH, wk, bk, nullptr, pK, MROWS, DD, DD);
    gemm_kernel<<<gD, gemmBlk>>>(pH, wv, bv, nullptr, pV, MROWS, DD, DD);

    // 3. attention
    attn_kernel<<<BB * HH * SS, 128>>>(pQ, pK, pV, abias, pAtt);

    // 4. O-proj + bias + residual(x)
    gemm_kernel<<<gD, gemmBlk>>>(pAtt, wo, bo, x, pRes1, MROWS, DD, DD);

    // 5. h2 = rmsnorm(res1, ln2_w)
    rmsnorm_kernel<<<MROWS, 256>>>(pRes1, ln2w, pH2);

    // 6/7. gate & up projections
    gemm_kernel<<<gI, gemmBlk>>>(pH2, w_gate, nullptr, nullptr, pGate, MROWS, II, DD);
    gemm_kernel<<<gI, gemmBlk>>>(pH2, w_up,   nullptr, nullptr, pUp,   MROWS, II, DD);

    // 8. act = silu(gate) * up
    size_t nact = (size_t)MROWS * II;
    swiglu_kernel<<<(unsigned)((nact + 255) / 256), 256>>>(pGate, pUp, nact);

    // 9. out = act @ w_down + res1
    gemm_kernel<<<gD, gemmBlk>>>(pGate, w_down, nullptr, pRes1, out, MROWS, DD, II);
}

// round 2
// speedup vs baseline: 3.5596x; 3.5596x over previous
#include <cuda_runtime.h>
#include <cuda_bf16.h>
#include <math.h>
#include <stdint.h>

// Problem constants
#define BB 2
#define SS 2048
#define DD 1024
#define HH 16
#define HDIM 64
#define II 3752
#define MROWS (BB*SS)          // 4096
#define EPS 1e-6f
#define FULLMASK 0xffffffffu

// ---------------- scratch (device globals) ----------------
__device__ float g_h   [MROWS * DD];
__device__ float g_q   [MROWS * DD];
__device__ float g_k   [MROWS * DD];
__device__ float g_v   [MROWS * DD];
__device__ float g_att [MROWS * DD];
__device__ float g_res1[MROWS * DD];
__device__ float g_h2  [MROWS * DD];
__device__ float g_gate[MROWS * II];
__device__ float g_up  [MROWS * II];

// ---------------- tf32 helpers ----------------
__device__ __forceinline__ uint32_t f2tf32(float f) {
    uint32_t r;
    asm("cvt.rna.tf32.f32 %0, %1;" : "=r"(r) : "f"(f));
    return r;
}

__device__ __forceinline__ void mma_tf32(float* d, const uint32_t* a, const uint32_t* b) {
    asm("mma.sync.aligned.m16n8k8.row.col.f32.tf32.tf32.f32 "
        "{%0,%1,%2,%3},{%4,%5,%6,%7},{%8,%9},{%0,%1,%2,%3};"
        : "+f"(d[0]), "+f"(d[1]), "+f"(d[2]), "+f"(d[3])
        : "r"(a[0]), "r"(a[1]), "r"(a[2]), "r"(a[3]), "r"(b[0]), "r"(b[1]));
}

// ---------------- RMSNorm ----------------
__global__ void rmsnorm_kernel(const float* __restrict__ x, const float* __restrict__ w,
                               float* __restrict__ out)
{
    int row = blockIdx.x;
    const float* xr = x + (size_t)row * DD;
    float sum = 0.f;
    for (int c = threadIdx.x; c < DD; c += 256) { float t = xr[c]; sum += t * t; }
    __shared__ float red[256];
    red[threadIdx.x] = sum;
    __syncthreads();
    for (int s = 128; s > 0; s >>= 1) {
        if (threadIdx.x < s) red[threadIdx.x] += red[threadIdx.x + s];
        __syncthreads();
    }
    float r = rsqrtf(red[0] * (1.0f / DD) + EPS);
    float* orow = out + (size_t)row * DD;
    for (int c = threadIdx.x; c < DD; c += 256) orow[c] = w[c] * (xr[c] * r);
}

// ---------------- tf32 tensor-core GEMM: C[M,N] = A[M,K] @ W[K,N] (+bias)(+res) ----------
// block 256 threads (8 warps), BM=128, BN=64, BK=16; warp tile 32x32.
#define GBM 128
#define GBN 64
#define GBK 16

__global__ __launch_bounds__(256) void gemm_tf32_kernel(
    const float* __restrict__ A, const float* __restrict__ W,
    const float* __restrict__ bias, const float* __restrict__ res,
    float* __restrict__ C, int M, int N, int K)
{
    __shared__ float As[GBK][GBM + 4];   // [k][m], stride 132
    __shared__ float Bs[GBK][GBN + 4];   // [k][n], stride 68

    const int tid  = threadIdx.x;
    const int lane = tid & 31;
    const int warp = tid >> 5;
    const int wm = warp >> 1;            // 0..3
    const int wn = warp & 1;             // 0..1
    const int grp = lane >> 2;           // 0..7
    const int tig = lane & 3;            // 0..3

    const int bm = blockIdx.y * GBM;
    const int bn = blockIdx.x * GBN;

    float acc[2][4][4];
    #pragma unroll
    for (int i = 0; i < 2; i++)
        #pragma unroll
        for (int j = 0; j < 4; j++)
            #pragma unroll
            for (int r = 0; r < 4; r++) acc[i][j][r] = 0.f;

    const int ar = tid >> 1;             // 0..127
    const int ac = (tid & 1) * 8;        // 0 or 8
    const int br = tid >> 4;             // 0..15
    const int bc = (tid & 15) * 4;       // 0..60

    for (int k0 = 0; k0 < K; k0 += GBK) {
        // A tile 128x16 -> As[k][m]
        #pragma unroll
        for (int u = 0; u < 2; u++) {
            int c = ac + u * 4;
            float4 a4 = make_float4(0.f, 0.f, 0.f, 0.f);
            if (k0 + c + 4 <= K)
                a4 = *(const float4*)&A[(size_t)(bm + ar) * K + k0 + c];
            As[c + 0][ar] = a4.x; As[c + 1][ar] = a4.y;
            As[c + 2][ar] = a4.z; As[c + 3][ar] = a4.w;
        }
        // B tile 16x64
        {
            float4 b4 = make_float4(0.f, 0.f, 0.f, 0.f);
            if ((k0 + br) < K && (bn + bc + 4) <= N)
                b4 = *(const float4*)&W[(size_t)(k0 + br) * N + bn + bc];
            *(float4*)&Bs[br][bc] = b4;
        }
        __syncthreads();

        #pragma unroll
        for (int ks = 0; ks < 2; ks++) {
            const int kb = ks * 8;
            uint32_t af[2][4];
            #pragma unroll
            for (int mt = 0; mt < 2; mt++) {
                int r0 = wm * 32 + mt * 16 + grp;
                af[mt][0] = f2tf32(As[kb + tig    ][r0    ]);
                af[mt][1] = f2tf32(As[kb + tig    ][r0 + 8]);
                af[mt][2] = f2tf32(As[kb + tig + 4][r0    ]);
                af[mt][3] = f2tf32(As[kb + tig + 4][r0 + 8]);
            }
            uint32_t bf[4][2];
            #pragma unroll
            for (int nt = 0; nt < 4; nt++) {
                int n0 = wn * 32 + nt * 8 + grp;
                bf[nt][0] = f2tf32(Bs[kb + tig    ][n0]);
                bf[nt][1] = f2tf32(Bs[kb + tig + 4][n0]);
            }
            #pragma unroll
            for (int mt = 0; mt < 2; mt++)
                #pragma unroll
                for (int nt = 0; nt < 4; nt++)
                    mma_tf32(acc[mt][nt], af[mt], bf[nt]);
        }
        __syncthreads();
    }

    // epilogue
    #pragma unroll
    for (int mt = 0; mt < 2; mt++) {
        int r0 = bm + wm * 32 + mt * 16 + grp;
        #pragma unroll
        for (int nt = 0; nt < 4; nt++) {
            int c0 = bn + wn * 32 + nt * 8 + 2 * tig;
            if (c0 < N) {
                float v0 = acc[mt][nt][0], v1 = acc[mt][nt][1];
                float v2 = acc[mt][nt][2], v3 = acc[mt][nt][3];
                if (bias) { v0 += bias[c0]; v1 += bias[c0 + 1]; v2 += bias[c0]; v3 += bias[c0 + 1]; }
                if (res) {
                    float2 r1_ = *(const float2*)&res[(size_t)r0 * N + c0];
                    float2 r2_ = *(const float2*)&res[(size_t)(r0 + 8) * N + c0];
                    v0 += r1_.x; v1 += r1_.y; v2 += r2_.x; v3 += r2_.y;
                }
                *(float2*)&C[(size_t)r0 * N + c0]       = make_float2(v0, v1);
                *(float2*)&C[(size_t)(r0 + 8) * N + c0] = make_float2(v2, v3);
            }
        }
    }
}

// ---------------- flash attention (tf32 mma, online softmax) ----------------
// block: 128 queries x 1 head; 8 warps, each warp owns 16 query rows.
// smem: sK[64][68], sV[64][68], sQP[128][68] (Q staging, then P per warp)
#define ATT_STRIDE 68
#define ATT_SMEM_FLOATS (64*ATT_STRIDE*2 + 128*ATT_STRIDE)
#define ATT_SMEM_BYTES (ATT_SMEM_FLOATS * 4)

__global__ __launch_bounds__(256, 1) void attn_kernel(
    const float* __restrict__ q, const float* __restrict__ k, const float* __restrict__ v,
    float* __restrict__ out)
{
    extern __shared__ float smem[];
    float* sK  = smem;                       // 64 x 68
    float* sV  = smem + 64 * ATT_STRIDE;     // 64 x 68
    float* sQP = smem + 128 * ATT_STRIDE;    // 128 x 68

    const int tid  = threadIdx.x;
    const int lane = tid & 31;
    const int warp = tid >> 5;
    const int grp  = lane >> 2;
    const int tig  = lane & 3;

    const int q0 = blockIdx.x * 128;
    const int h  = blockIdx.y;
    const int b  = blockIdx.z;

    const float slope = -exp2f(-0.5f * (float)(h + 1));

    // ---- stage Q tile ----
    const float* qbase = q + ((size_t)(b * SS + q0) * HH + h) * HDIM;
    #pragma unroll
    for (int it = 0; it < 8; it++) {
        int idx = it * 256 + tid;
        int r = idx >> 4, c4 = (idx & 15) * 4;
        *(float4*)&sQP[r * ATT_STRIDE + c4] = *(const float4*)&qbase[(size_t)r * (HH * HDIM) + c4];
    }
    __syncthreads();

    // ---- build Q frags (scaled by 1/8 = HD^-0.5) ----
    const int myr = warp * 16 + grp;
    uint32_t qf[8][4];
    #pragma unroll
    for (int ks = 0; ks < 8; ks++) {
        qf[ks][0] = f2tf32(0.125f * sQP[(myr    ) * ATT_STRIDE + ks * 8 + tig    ]);
        qf[ks][1] = f2tf32(0.125f * sQP[(myr + 8) * ATT_STRIDE + ks * 8 + tig    ]);
        qf[ks][2] = f2tf32(0.125f * sQP[(myr    ) * ATT_STRIDE + ks * 8 + tig + 4]);
        qf[ks][3] = f2tf32(0.125f * sQP[(myr + 8) * ATT_STRIDE + ks * 8 + tig + 4]);
    }
    __syncthreads();

    const int row0 = q0 + warp * 16 + grp;
    const int row1 = row0 + 8;
    const int warp_max_row = q0 + warp * 16 + 15;

    float m0 = -INFINITY, m1 = -INFINITY, l0 = 0.f, l1 = 0.f;
    float oacc[8][4];
    #pragma unroll
    for (int nt = 0; nt < 8; nt++)
        #pragma unroll
        for (int r = 0; r < 4; r++) oacc[nt][r] = 0.f;

    const int nkt = (q0 >> 6) + 2;
    const float* kbase0 = k + ((size_t)(b * SS) * HH + h) * HDIM;
    const float* vbase0 = v + ((size_t)(b * SS) * HH + h) * HDIM;

    for (int kt = 0; kt < nkt; kt++) {
        const int j0 = kt * 64;
        // ---- stage K,V tiles ----
        const float* kb_ = kbase0 + (size_t)j0 * (HH * HDIM);
        const float* vb_ = vbase0 + (size_t)j0 * (HH * HDIM);
        #pragma unroll
        for (int it = 0; it < 4; it++) {
            int idx = it * 256 + tid;
            int r = idx >> 4, c4 = (idx & 15) * 4;
            *(float4*)&sK[r * ATT_STRIDE + c4] = *(const float4*)&kb_[(size_t)r * (HH * HDIM) + c4];
            *(float4*)&sV[r * ATT_STRIDE + c4] = *(const float4*)&vb_[(size_t)r * (HH * HDIM) + c4];
        }
        __syncthreads();

        if (j0 <= warp_max_row) {
            // ---- S = Q @ K^T ----
            float sacc[8][4];
            #pragma unroll
            for (int nt = 0; nt < 8; nt++)
                #pragma unroll
                for (int r = 0; r < 4; r++) sacc[nt][r] = 0.f;

            #pragma unroll
            for (int ks = 0; ks < 8; ks++) {
                uint32_t bf[8][2];
                #pragma unroll
                for (int nt = 0; nt < 8; nt++) {
                    bf[nt][0] = f2tf32(sK[(nt * 8 + grp) * ATT_STRIDE + ks * 8 + tig    ]);
                    bf[nt][1] = f2tf32(sK[(nt * 8 + grp) * ATT_STRIDE + ks * 8 + tig + 4]);
                }
                #pragma unroll
                for (int nt = 0; nt < 8; nt++)
                    mma_tf32(sacc[nt], qf[ks], bf[nt]);
            }

            // ---- bias + causal mask ----
            float mn0 = m0, mn1 = m1;
            #pragma unroll
            for (int nt = 0; nt < 8; nt++) {
                int cbase = j0 + nt * 8 + 2 * tig;
                #pragma unroll
                for (int r = 0; r < 4; r++) {
                    int col = cbase + (r & 1);
                    int rw = (r < 2) ? row0 : row1;
                    float s;
                    if (col > rw) s = -INFINITY;
                    else          s = sacc[nt][r] + slope * (float)(rw - col);
                    sacc[nt][r] = s;
                    if (r < 2) mn0 = fmaxf(mn0, s); else mn1 = fmaxf(mn1, s);
                }
            }
            // quad reduce max
            mn0 = fmaxf(mn0, __shfl_xor_sync(FULLMASK, mn0, 1));
            mn0 = fmaxf(mn0, __shfl_xor_sync(FULLMASK, mn0, 2));
            mn1 = fmaxf(mn1, __shfl_xor_sync(FULLMASK, mn1, 1));
            mn1 = fmaxf(mn1, __shfl_xor_sync(FULLMASK, mn1, 2));

            float f0 = __expf(m0 - mn0);
            float f1 = __expf(m1 - mn1);
            m0 = mn0; m1 = mn1;

            // ---- P = exp(S - m), rowsum ----
            float rs0 = 0.f, rs1 = 0.f;
            #pragma unroll
            for (int nt = 0; nt < 8; nt++) {
                float p0 = __expf(sacc[nt][0] - m0);
                float p1 = __expf(sacc[nt][1] - m0);
                float p2 = __expf(sacc[nt][2] - m1);
                float p3 = __expf(sacc[nt][3] - m1);
                sacc[nt][0] = p0; sacc[nt][1] = p1; sacc[nt][2] = p2; sacc[nt][3] = p3;
                rs0 += p0 + p1; rs1 += p2 + p3;
            }
            rs0 += __shfl_xor_sync(FULLMASK, rs0, 1);
            rs0 += __shfl_xor_sync(FULLMASK, rs0, 2);
            rs1 += __shfl_xor_sync(FULLMASK, rs1, 1);
            rs1 += __shfl_xor_sync(FULLMASK, rs1, 2);
            l0 = l0 * f0 + rs0;
            l1 = l1 * f1 + rs1;

            // ---- rescale O ----
            #pragma unroll
            for (int nt = 0; nt < 8; nt++) {
                oacc[nt][0] *= f0; oacc[nt][1] *= f0;
                oacc[nt][2] *= f1; oacc[nt][3] *= f1;
            }

            // ---- P -> smem (warp-private region), re-fragment ----
            #pragma unroll
            for (int nt = 0; nt < 8; nt++) {
                *(float2*)&sQP[(myr    ) * ATT_STRIDE + nt * 8 + 2 * tig] = make_float2(sacc[nt][0], sacc[nt][1]);
                *(float2*)&sQP[(myr + 8) * ATT_STRIDE + nt * 8 + 2 * tig] = make_float2(sacc[nt][2], sacc[nt][3]);
            }
            __syncwarp();

            // ---- O += P @ V ----
            #pragma unroll
            for (int ks = 0; ks < 8; ks++) {
                uint32_t pf[4];
                pf[0] = f2tf32(sQP[(myr    ) * ATT_STRIDE + ks * 8 + tig    ]);
                pf[1] = f2tf32(sQP[(myr + 8) * ATT_STRIDE + ks * 8 + tig    ]);
                pf[2] = f2tf32(sQP[(myr    ) * ATT_STRIDE + ks * 8 + tig + 4]);
                pf[3] = f2tf32(sQP[(myr + 8) * ATT_STRIDE + ks * 8 + tig + 4]);
                uint32_t vf[8][2];
                #pragma unroll
                for (int nt = 0; nt < 8; nt++) {
                    vf[nt][0] = f2tf32(sV[(ks * 8 + tig    ) * ATT_STRIDE + nt * 8 + grp]);
                    vf[nt][1] = f2tf32(sV[(ks * 8 + tig + 4) * ATT_STRIDE + nt * 8 + grp]);
                }
                #pragma unroll
                for (int nt = 0; nt < 8; nt++)
                    mma_tf32(oacc[nt], pf, vf[nt]);
            }
        }
        __syncthreads();
    }

    // ---- write O / l ----
    float inv0 = 1.0f / l0, inv1 = 1.0f / l1;
    float* obase = out + ((size_t)(b * SS) * HH + h) * HDIM;
    #pragma unroll
    for (int nt = 0; nt < 8; nt++) {
        int d = nt * 8 + 2 * tig;
        *(float2*)&obase[(size_t)row0 * (HH * HDIM) + d] = make_float2(oacc[nt][0] * inv0, oacc[nt][1] * inv0);
        *(float2*)&obase[(size_t)row1 * (HH * HDIM) + d] = make_float2(oacc[nt][2] * inv1, oacc[nt][3] * inv1);
    }
}

// ---------------- SwiGLU elementwise ----------------
__global__ void swiglu_kernel(float* __restrict__ gate, const float* __restrict__ up, size_t n)
{
    size_t idx = (size_t)blockIdx.x * blockDim.x + threadIdx.x;
    if (idx < n) {
        float g = gate[idx];
        float s = g / (1.0f + __expf(-g));
        gate[idx] = s * up[idx];
    }
}

// ---------------- launch ----------------
extern "C" void kernel_launch(void* const* d_in, const int* in_sizes, int n_in,
                              void* d_out, int out_size)
{
    const float* x      = (const float*)d_in[0];
    const float* wq     = (const float*)d_in[1];
    const float* bq     = (const float*)d_in[2];
    const float* wk     = (const float*)d_in[3];
    const float* bk     = (const float*)d_in[4];
    const float* wv     = (const float*)d_in[5];
    const float* bv     = (const float*)d_in[6];
    const float* wo     = (const float*)d_in[7];
    const float* bo     = (const float*)d_in[8];
    const float* w_gate = (const float*)d_in[9];
    const float* w_up   = (const float*)d_in[10];
    const float* w_down = (const float*)d_in[11];
    const float* ln1w   = (const float*)d_in[12];
    const float* ln2w   = (const float*)d_in[13];
    float* out = (float*)d_out;

    static float *pH = nullptr, *pQ, *pK, *pV, *pAtt, *pRes1, *pH2, *pGate, *pUp;
    if (!pH) {
        cudaGetSymbolAddress((void**)&pH,    g_h);
        cudaGetSymbolAddress((void**)&pQ,    g_q);
        cudaGetSymbolAddress((void**)&pK,    g_k);
        cudaGetSymbolAddress((void**)&pV,    g_v);
        cudaGetSymbolAddress((void**)&pAtt,  g_att);
        cudaGetSymbolAddress((void**)&pRes1, g_res1);
        cudaGetSymbolAddress((void**)&pH2,   g_h2);
        cudaGetSymbolAddress((void**)&pGate, g_gate);
        cudaGetSymbolAddress((void**)&pUp,   g_up);
        cudaFuncSetAttribute(attn_kernel, cudaFuncAttributeMaxDynamicSharedMemorySize, ATT_SMEM_BYTES);
    }

    dim3 blk(256);
    dim3 gD(DD / GBN, MROWS / GBM);                   // 16 x 32
    dim3 gI((II + GBN - 1) / GBN, MROWS / GBM);       // 59 x 32

    // 1. h = rmsnorm(x, ln1_w)
    rmsnorm_kernel<<<MROWS, 256>>>(x, ln1w, pH);

    // 2. q,k,v projections (tf32 mma)
    gemm_tf32_kernel<<<gD, blk>>>(pH, wq, bq, nullptr, pQ, MROWS, DD, DD);
    gemm_tf32_kernel<<<gD, blk>>>(pH, wk, bk, nullptr, pK, MROWS, DD, DD);
    gemm_tf32_kernel<<<gD, blk>>>(pH, wv, bv, nullptr, pV, MROWS, DD, DD);

    // 3. flash attention
    dim3 ga(SS / 128, HH, BB);
    attn_kernel<<<ga, 256, ATT_SMEM_BYTES>>>(pQ, pK, pV, pAtt);

    // 4. O-proj + bias + residual(x)
    gemm_tf32_kernel<<<gD, blk>>>(pAtt, wo, bo, x, pRes1, MROWS, DD, DD);

    // 5. h2 = rmsnorm(res1, ln2_w)
    rmsnorm_kernel<<<MROWS, 256>>>(pRes1, ln2w, pH2);

    // 6/7. gate & up projections
    gemm_tf32_kernel<<<gI, blk>>>(pH2, w_gate, nullptr, nullptr, pGate, MROWS, II, DD);
    gemm_tf32_kernel<<<gI, blk>>>(pH2, w_up,   nullptr, nullptr, pUp,   MROWS, II, DD);

    // 8. act = silu(gate) * up
    size_t nact = (size_t)MROWS * II;
    swiglu_kernel<<<(unsigned)((nact + 255) / 256), 256>>>(pGate, pUp, nact);

    // 9. out = act @ w_down + res1
    gemm_tf32_kernel<<<gD, blk>>>(pGate, w_down, nullptr, pRes1, out, MROWS, DD, II);
}

// round 3
// speedup vs baseline: 7.0650x; 1.9848x over previous
#include <cuda_runtime.h>
#include <cuda_bf16.h>
#include <math.h>
#include <stdint.h>

// Problem constants
#define BB 2
#define SS 2048
#define DD 1024
#define HH 16
#define HDIM 64
#define II 3752
#define MROWS (BB*SS)          // 4096
#define EPS 1e-6f
#define FULLMASK 0xffffffffu

// ---------------- scratch (device globals) ----------------
__device__ float g_h   [MROWS * DD];
__device__ float g_q   [MROWS * DD];
__device__ float g_k   [MROWS * DD];
__device__ float g_v   [MROWS * DD];
__device__ float g_att [MROWS * DD];
__device__ float g_res1[MROWS * DD];
__device__ float g_h2  [MROWS * DD];
__device__ float g_gate[MROWS * II];
__device__ float g_act [MROWS * II];
// converted (tf32-rounded) weights
__device__ float g_cw  [4 * DD * DD + 3 * DD * II];

#define CW_Q  0
#define CW_K  (DD*DD)
#define CW_V  (2*DD*DD)
#define CW_O  (3*DD*DD)
#define CW_G  (4*DD*DD)
#define CW_U  (4*DD*DD + DD*II)
#define CW_D  (4*DD*DD + 2*DD*II)

// ---------------- tf32 helpers ----------------
__device__ __forceinline__ uint32_t f2tf32(float f) {
    uint32_t r;
    asm("cvt.rna.tf32.f32 %0, %1;" : "=r"(r) : "f"(f));
    return r;
}
__device__ __forceinline__ float tf32r(float f) { return __uint_as_float(f2tf32(f)); }

__device__ __forceinline__ void mma_tf32(float* d, const uint32_t* a, const uint32_t* b) {
    asm("mma.sync.aligned.m16n8k8.row.col.f32.tf32.tf32.f32 "
        "{%0,%1,%2,%3},{%4,%5,%6,%7},{%8,%9},{%0,%1,%2,%3};"
        : "+f"(d[0]), "+f"(d[1]), "+f"(d[2]), "+f"(d[3])
        : "r"(a[0]), "r"(a[1]), "r"(a[2]), "r"(a[3]), "r"(b[0]), "r"(b[1]));
}

#define CP_ASYNC(dst, src, sz) \
    asm volatile("cp.async.cg.shared.global [%0], [%1], 16, %2;\n" :: "r"(dst), "l"(src), "r"(sz))
#define CP_COMMIT asm volatile("cp.async.commit_group;\n" ::)
#define CP_WAIT1  asm volatile("cp.async.wait_group 1;\n" ::)

// ---------------- weight convert (round to tf32 once) ----------------
__global__ void cvt_kernel(const float* __restrict__ src, float* __restrict__ dst, int n4)
{
    int i = blockIdx.x * 256 + threadIdx.x;
    if (i < n4) {
        float4 v = ((const float4*)src)[i];
        v.x = tf32r(v.x); v.y = tf32r(v.y); v.z = tf32r(v.z); v.w = tf32r(v.w);
        ((float4*)dst)[i] = v;
    }
}

// ---------------- RMSNorm (output tf32-rounded) ----------------
__global__ void rmsnorm_kernel(const float* __restrict__ x, const float* __restrict__ w,
                               float* __restrict__ out)
{
    int row = blockIdx.x;
    const float* xr = x + (size_t)row * DD;
    float sum = 0.f;
    for (int c = threadIdx.x; c < DD; c += 256) { float t = xr[c]; sum += t * t; }
    __shared__ float red[256];
    red[threadIdx.x] = sum;
    __syncthreads();
    for (int s = 128; s > 0; s >>= 1) {
        if (threadIdx.x < s) red[threadIdx.x] += red[threadIdx.x + s];
        __syncthreads();
    }
    float r = rsqrtf(red[0] * (1.0f / DD) + EPS);
    float* orow = out + (size_t)row * DD;
    for (int c = threadIdx.x; c < DD; c += 256) orow[c] = tf32r(w[c] * (xr[c] * r));
}

// ---------------- pipelined tf32 GEMM: C[M,N] = A @ W (+bias)(+silu(gate)*)(+res) ----
// 128x128 block tile, BK=16, 8 warps (2x4), warp tile 64x32, 3-stage cp.async.
#define GBM 128
#define GBN 128
#define GBK 16
#define ASTRIDE 20
#define BSTRIDE 136
#define ASZ (GBM*ASTRIDE)      // 2560
#define BSZ (GBK*BSTRIDE)      // 2176
#define STG (ASZ+BSZ)          // 4736 floats per stage
#define GEMM_SMEM_BYTES (3*STG*4)

__device__ __forceinline__ void gemm_load_stage(
    const float* __restrict__ A, const float* __restrict__ W,
    int N, int K, int bm, int bn, int k0, float* sA, float* sB, int tid)
{
    #pragma unroll
    for (int u = 0; u < 2; u++) {
        int id = tid + u * 256;
        int row = id >> 2, cc = (id & 3) * 4;
        int kk = k0 + cc;
        int sz = (kk + 4 <= K) ? 16 : 0;
        const float* src = A + (size_t)(bm + row) * K + (sz ? kk : 0);
        uint32_t dst = (uint32_t)__cvta_generic_to_shared(sA + row * ASTRIDE + cc);
        CP_ASYNC(dst, src, sz);
    }
    #pragma unroll
    for (int u = 0; u < 2; u++) {
        int id = tid + u * 256;
        int row = id >> 5, cc = (id & 31) * 4;
        int kk = k0 + row, col = bn + cc;
        int sz = (kk < K && col + 4 <= N) ? 16 : 0;
        const float* src = W + (sz ? ((size_t)kk * N + col) : 0);
        uint32_t dst = (uint32_t)__cvta_generic_to_shared(sB + row * BSTRIDE + cc);
        CP_ASYNC(dst, src, sz);
    }
}

__global__ __launch_bounds__(256) void gemm_tf32_kernel(
    const float* __restrict__ A, const float* __restrict__ W,
    const float* __restrict__ bias, const float* __restrict__ res,
    const float* __restrict__ gate, float* __restrict__ C,
    int M, int N, int K, int roundout)
{
    extern __shared__ float smem[];

    const int tid  = threadIdx.x;
    const int lane = tid & 31;
    const int warp = tid >> 5;
    const int wm = warp >> 2;            // 0..1 -> 64 rows
    const int wn = warp & 3;             // 0..3 -> 32 cols
    const int grp = lane >> 2;           // 0..7
    const int tig = lane & 3;            // 0..3

    const int bm = blockIdx.y * GBM;
    const int bn = blockIdx.x * GBN;

    float acc[4][4][4];
    #pragma unroll
    for (int i = 0; i < 4; i++)
        #pragma unroll
        for (int j = 0; j < 4; j++)
            #pragma unroll
            for (int r = 0; r < 4; r++) acc[i][j][r] = 0.f;

    const int T = (K + GBK - 1) / GBK;

    gemm_load_stage(A, W, N, K, bm, bn, 0, smem, smem + ASZ, tid);
    CP_COMMIT;
    gemm_load_stage(A, W, N, K, bm, bn, GBK, smem + STG, smem + STG + ASZ, tid);
    CP_COMMIT;

    for (int t = 0; t < T; t++) {
        CP_WAIT1;
        __syncthreads();

        const float* sA = smem + (t % 3) * STG;
        const float* sB = sA + ASZ;

        #pragma unroll
        for (int ks = 0; ks < 2; ks++) {
            const int kb = ks * 8;
            uint32_t af[4][4];
            #pragma unroll
            for (int mt = 0; mt < 4; mt++) {
                const float* p = sA + (wm * 64 + mt * 16 + grp) * ASTRIDE + kb + tig;
                af[mt][0] = __float_as_uint(p[0]);
                af[mt][1] = __float_as_uint(p[8 * ASTRIDE]);
                af[mt][2] = __float_as_uint(p[4]);
                af[mt][3] = __float_as_uint(p[8 * ASTRIDE + 4]);
            }
            uint32_t bf[4][2];
            #pragma unroll
            for (int nt = 0; nt < 4; nt++) {
                const float* p = sB + (kb + tig) * BSTRIDE + wn * 32 + nt * 8 + grp;
                bf[nt][0] = __float_as_uint(p[0]);
                bf[nt][1] = __float_as_uint(p[4 * BSTRIDE]);
            }
            #pragma unroll
            for (int mt = 0; mt < 4; mt++)
                #pragma unroll
                for (int nt = 0; nt < 4; nt++)
                    mma_tf32(acc[mt][nt], af[mt], bf[nt]);
        }

        if (t + 2 < T) {
            float* dA = smem + ((t + 2) % 3) * STG;
            gemm_load_stage(A, W, N, K, bm, bn, (t + 2) * GBK, dA, dA + ASZ, tid);
        }
        CP_COMMIT;
    }

    // ---- epilogue ----
    #pragma unroll
    for (int mt = 0; mt < 4; mt++) {
        int r0 = bm + wm * 64 + mt * 16 + grp;
        #pragma unroll
        for (int nt = 0; nt < 4; nt++) {
            int c0 = bn + wn * 32 + nt * 8 + 2 * tig;
            if (c0 >= N) continue;
            float v0 = acc[mt][nt][0], v1 = acc[mt][nt][1];
            float v2 = acc[mt][nt][2], v3 = acc[mt][nt][3];
            if (bias) {
                float b0 = bias[c0], b1 = bias[c0 + 1];
                v0 += b0; v1 += b1; v2 += b0; v3 += b1;
            }
            if (gate) {
                float2 ga = *(const float2*)&gate[(size_t)r0 * N + c0];
                float2 gb = *(const float2*)&gate[(size_t)(r0 + 8) * N + c0];
                v0 *= ga.x / (1.0f + __expf(-ga.x));
                v1 *= ga.y / (1.0f + __expf(-ga.y));
                v2 *= gb.x / (1.0f + __expf(-gb.x));
                v3 *= gb.y / (1.0f + __expf(-gb.y));
            }
            if (res) {
                float2 ra = *(const float2*)&res[(size_t)r0 * N + c0];
                float2 rb = *(const float2*)&res[(size_t)(r0 + 8) * N + c0];
                v0 += ra.x; v1 += ra.y; v2 += rb.x; v3 += rb.y;
            }
            if (roundout) { v0 = tf32r(v0); v1 = tf32r(v1); v2 = tf32r(v2); v3 = tf32r(v3); }
            *(float2*)&C[(size_t)r0 * N + c0]       = make_float2(v0, v1);
            *(float2*)&C[(size_t)(r0 + 8) * N + c0] = make_float2(v2, v3);
        }
    }
}

// ---------------- flash attention (tf32 mma, online softmax) ----------------
// inputs q,k,v are pre-rounded to tf32; outputs rounded to tf32.
#define ATT_STRIDE 72
#define ATT_SMEM_BYTES ((64*ATT_STRIDE*2 + 128*ATT_STRIDE) * 4)

__global__ __launch_bounds__(256, 1) void attn_kernel(
    const float* __restrict__ q, const float* __restrict__ k, const float* __restrict__ v,
    float* __restrict__ out)
{
    extern __shared__ float smem[];
    float* sK  = smem;                       // 64 x 72
    float* sV  = smem + 64 * ATT_STRIDE;     // 64 x 72
    float* sQP = smem + 128 * ATT_STRIDE;    // 128 x 72

    const int tid  = threadIdx.x;
    const int lane = tid & 31;
    const int warp = tid >> 5;
    const int grp  = lane >> 2;
    const int tig  = lane & 3;

    const int q0 = blockIdx.x * 128;
    const int h  = blockIdx.y;
    const int b  = blockIdx.z;

    const float slope = -exp2f(-0.5f * (float)(h + 1));

    // ---- stage Q tile ----
    const float* qbase = q + ((size_t)(b * SS + q0) * HH + h) * HDIM;
    #pragma unroll
    for (int it = 0; it < 8; it++) {
        int idx = it * 256 + tid;
        int r = idx >> 4, c4 = (idx & 15) * 4;
        *(float4*)&sQP[r * ATT_STRIDE + c4] = *(const float4*)&qbase[(size_t)r * (HH * HDIM) + c4];
    }
    __syncthreads();

    // ---- build Q frags (scaled by 1/8; exact power of two keeps tf32) ----
    const int myr = warp * 16 + grp;
    uint32_t qf[8][4];
    #pragma unroll
    for (int ks = 0; ks < 8; ks++) {
        qf[ks][0] = __float_as_uint(0.125f * sQP[(myr    ) * ATT_STRIDE + ks * 8 + tig    ]);
        qf[ks][1] = __float_as_uint(0.125f * sQP[(myr + 8) * ATT_STRIDE + ks * 8 + tig    ]);
        qf[ks][2] = __float_as_uint(0.125f * sQP[(myr    ) * ATT_STRIDE + ks * 8 + tig + 4]);
        qf[ks][3] = __float_as_uint(0.125f * sQP[(myr + 8) * ATT_STRIDE + ks * 8 + tig + 4]);
    }
    __syncthreads();

    const int row0 = q0 + warp * 16 + grp;
    const int row1 = row0 + 8;
    const int warp_max_row = q0 + warp * 16 + 15;

    float m0 = -INFINITY, m1 = -INFINITY, l0 = 0.f, l1 = 0.f;
    float oacc[8][4];
    #pragma unroll
    for (int nt = 0; nt < 8; nt++)
        #pragma unroll
        for (int r = 0; r < 4; r++) oacc[nt][r] = 0.f;

    const int nkt = (q0 >> 6) + 2;
    const float* kbase0 = k + ((size_t)(b * SS) * HH + h) * HDIM;
    const float* vbase0 = v + ((size_t)(b * SS) * HH + h) * HDIM;

    for (int kt = 0; kt < nkt; kt++) {
        const int j0 = kt * 64;
        const float* kb_ = kbase0 + (size_t)j0 * (HH * HDIM);
        const float* vb_ = vbase0 + (size_t)j0 * (HH * HDIM);
        #pragma unroll
        for (int it = 0; it < 4; it++) {
            int idx = it * 256 + tid;
            int r = idx >> 4, c4 = (idx & 15) * 4;
            *(float4*)&sK[r * ATT_STRIDE + c4] = *(const float4*)&kb_[(size_t)r * (HH * HDIM) + c4];
            *(float4*)&sV[r * ATT_STRIDE + c4] = *(const float4*)&vb_[(size_t)r * (HH * HDIM) + c4];
        }
        __syncthreads();

        if (j0 <= warp_max_row) {
            // ---- S = Q @ K^T ----
            float sacc[8][4];
            #pragma unroll
            for (int nt = 0; nt < 8; nt++)
                #pragma unroll
                for (int r = 0; r < 4; r++) sacc[nt][r] = 0.f;

            #pragma unroll
            for (int ks = 0; ks < 8; ks++) {
                uint32_t bf[8][2];
                #pragma unroll
                for (int nt = 0; nt < 8; nt++) {
                    bf[nt][0] = __float_as_uint(sK[(nt * 8 + grp) * ATT_STRIDE + ks * 8 + tig    ]);
                    bf[nt][1] = __float_as_uint(sK[(nt * 8 + grp) * ATT_STRIDE + ks * 8 + tig + 4]);
                }
                #pragma unroll
                for (int nt = 0; nt < 8; nt++)
                    mma_tf32(sacc[nt], qf[ks], bf[nt]);
            }

            // ---- bias + causal mask ----
            float mn0 = m0, mn1 = m1;
            #pragma unroll
            for (int nt = 0; nt < 8; nt++) {
                int cbase = j0 + nt * 8 + 2 * tig;
                #pragma unroll
                for (int r = 0; r < 4; r++) {
                    int col = cbase + (r & 1);
                    int rw = (r < 2) ? row0 : row1;
                    float s;
                    if (col > rw) s = -INFINITY;
                    else          s = sacc[nt][r] + slope * (float)(rw - col);
                    sacc[nt][r] = s;
                    if (r < 2) mn0 = fmaxf(mn0, s); else mn1 = fmaxf(mn1, s);
                }
            }
            mn0 = fmaxf(mn0, __shfl_xor_sync(FULLMASK, mn0, 1));
            mn0 = fmaxf(mn0, __shfl_xor_sync(FULLMASK, mn0, 2));
            mn1 = fmaxf(mn1, __shfl_xor_sync(FULLMASK, mn1, 1));
            mn1 = fmaxf(mn1, __shfl_xor_sync(FULLMASK, mn1, 2));

            float f0 = __expf(m0 - mn0);
            float f1 = __expf(m1 - mn1);
            m0 = mn0; m1 = mn1;

            float rs0 = 0.f, rs1 = 0.f;
            #pragma unroll
            for (int nt = 0; nt < 8; nt++) {
                float p0 = __expf(sacc[nt][0] - m0);
                float p1 = __expf(sacc[nt][1] - m0);
                float p2 = __expf(sacc[nt][2] - m1);
                float p3 = __expf(sacc[nt][3] - m1);
                sacc[nt][0] = p0; sacc[nt][1] = p1; sacc[nt][2] = p2; sacc[nt][3] = p3;
                rs0 += p0 + p1; rs1 += p2 + p3;
            }
            rs0 += __shfl_xor_sync(FULLMASK, rs0, 1);
            rs0 += __shfl_xor_sync(FULLMASK, rs0, 2);
            rs1 += __shfl_xor_sync(FULLMASK, rs1, 1);
            rs1 += __shfl_xor_sync(FULLMASK, rs1, 2);
            l0 = l0 * f0 + rs0;
            l1 = l1 * f1 + rs1;

            #pragma unroll
            for (int nt = 0; nt < 8; nt++) {
                oacc[nt][0] *= f0; oacc[nt][1] *= f0;
                oacc[nt][2] *= f1; oacc[nt][3] *= f1;
            }

            // ---- P -> warp-private smem, re-fragment ----
            #pragma unroll
            for (int nt = 0; nt < 8; nt++) {
                *(float2*)&sQP[(myr    ) * ATT_STRIDE + nt * 8 + 2 * tig] = make_float2(sacc[nt][0], sacc[nt][1]);
                *(float2*)&sQP[(myr + 8) * ATT_STRIDE + nt * 8 + 2 * tig] = make_float2(sacc[nt][2], sacc[nt][3]);
            }
            __syncwarp();

            #pragma unroll
            for (int ks = 0; ks < 8; ks++) {
                uint32_t pf[4];
                pf[0] = f2tf32(sQP[(myr    ) * ATT_STRIDE + ks * 8 + tig    ]);
                pf[1] = f2tf32(sQP[(myr + 8) * ATT_STRIDE + ks * 8 + tig    ]);
                pf[2] = f2tf32(sQP[(myr    ) * ATT_STRIDE + ks * 8 + tig + 4]);
                pf[3] = f2tf32(sQP[(myr + 8) * ATT_STRIDE + ks * 8 + tig + 4]);
                uint32_t vf[8][2];
                #pragma unroll
                for (int nt = 0; nt < 8; nt++) {
                    vf[nt][0] = __float_as_uint(sV[(ks * 8 + tig    ) * ATT_STRIDE + nt * 8 + grp]);
                    vf[nt][1] = __float_as_uint(sV[(ks * 8 + tig + 4) * ATT_STRIDE + nt * 8 + grp]);
                }
                #pragma unroll
                for (int nt = 0; nt < 8; nt++)
                    mma_tf32(oacc[nt], pf, vf[nt]);
            }
        }
        __syncthreads();
    }

    // ---- write O (tf32-rounded; feeds O-proj GEMM) ----
    float inv0 = 1.0f / l0, inv1 = 1.0f / l1;
    float* obase = out + ((size_t)(b * SS) * HH + h) * HDIM;
    #pragma unroll
    for (int nt = 0; nt < 8; nt++) {
        int d = nt * 8 + 2 * tig;
        *(float2*)&obase[(size_t)row0 * (HH * HDIM) + d] =
            make_float2(tf32r(oacc[nt][0] * inv0), tf32r(oacc[nt][1] * inv0));
        *(float2*)&obase[(size_t)row1 * (HH * HDIM) + d] =
            make_float2(tf32r(oacc[nt][2] * inv1), tf32r(oacc[nt][3] * inv1));
    }
}

// ---------------- launch ----------------
extern "C" void kernel_launch(void* const* d_in, const int* in_sizes, int n_in,
                              void* d_out, int out_size)
{
    const float* x      = (const float*)d_in[0];
    const float* wq     = (const float*)d_in[1];
    const float* bq     = (const float*)d_in[2];
    const float* wk     = (const float*)d_in[3];
    const float* bk     = (const float*)d_in[4];
    const float* wv     = (const float*)d_in[5];
    const float* bv     = (const float*)d_in[6];
    const float* wo     = (const float*)d_in[7];
    const float* bo     = (const float*)d_in[8];
    const float* w_gate = (const float*)d_in[9];
    const float* w_up   = (const float*)d_in[10];
    const float* w_down = (const float*)d_in[11];
    const float* ln1w   = (const float*)d_in[12];
    const float* ln2w   = (const float*)d_in[13];
    float* out = (float*)d_out;

    static float *pH = nullptr, *pQ, *pK, *pV, *pAtt, *pRes1, *pH2, *pGate, *pAct, *pCW;
    if (!pH) {
        cudaGetSymbolAddress((void**)&pH,    g_h);
        cudaGetSymbolAddress((void**)&pQ,    g_q);
        cudaGetSymbolAddress((void**)&pK,    g_k);
        cudaGetSymbolAddress((void**)&pV,    g_v);
        cudaGetSymbolAddress((void**)&pAtt,  g_att);
        cudaGetSymbolAddress((void**)&pRes1, g_res1);
        cudaGetSymbolAddress((void**)&pH2,   g_h2);
        cudaGetSymbolAddress((void**)&pGate, g_gate);
        cudaGetSymbolAddress((void**)&pAct,  g_act);
        cudaGetSymbolAddress((void**)&pCW,   g_cw);
        cudaFuncSetAttribute(attn_kernel, cudaFuncAttributeMaxDynamicSharedMemorySize, ATT_SMEM_BYTES);
        cudaFuncSetAttribute(gemm_tf32_kernel, cudaFuncAttributeMaxDynamicSharedMemorySize, GEMM_SMEM_BYTES);
    }

    // 0. round weights to tf32 once per replay
    const int nDD4 = DD * DD / 4, nDI4 = DD * II / 4;
    cvt_kernel<<<(nDD4 + 255) / 256, 256>>>(wq,     pCW + CW_Q, nDD4);
    cvt_kernel<<<(nDD4 + 255) / 256, 256>>>(wk,     pCW + CW_K, nDD4);
    cvt_kernel<<<(nDD4 + 255) / 256, 256>>>(wv,     pCW + CW_V, nDD4);
    cvt_kernel<<<(nDD4 + 255) / 256, 256>>>(wo,     pCW + CW_O, nDD4);
    cvt_kernel<<<(nDI4 + 255) / 256, 256>>>(w_gate, pCW + CW_G, nDI4);
    cvt_kernel<<<(nDI4 + 255) / 256, 256>>>(w_up,   pCW + CW_U, nDI4);
    cvt_kernel<<<(nDI4 + 255) / 256, 256>>>(w_down, pCW + CW_D, nDI4);

    dim3 blk(256);
    dim3 gD(DD / GBN, MROWS / GBM);                    // 8 x 32
    dim3 gI((II + GBN - 1) / GBN, MROWS / GBM);        // 30 x 32
    const int RND = 1, NORND = 0;

    // 1. h = rmsnorm(x) (tf32)
    rmsnorm_kernel<<<MROWS, 256>>>(x, ln1w, pH);

    // 2. q,k,v projections (outputs tf32)
    gemm_tf32_kernel<<<gD, blk, GEMM_SMEM_BYTES>>>(pH, pCW + CW_Q, bq, nullptr, nullptr, pQ, MROWS, DD, DD, RND);
    gemm_tf32_kernel<<<gD, blk, GEMM_SMEM_BYTES>>>(pH, pCW + CW_K, bk, nullptr, nullptr, pK, MROWS, DD, DD, RND);
    gemm_tf32_kernel<<<gD, blk, GEMM_SMEM_BYTES>>>(pH, pCW + CW_V, bv, nullptr, nullptr, pV, MROWS, DD, DD, RND);

    // 3. flash attention (output tf32)
    dim3 ga(SS / 128, HH, BB);
    attn_kernel<<<ga, 256, ATT_SMEM_BYTES>>>(pQ, pK, pV, pAtt);

    // 4. res1 = att @ wo + bo + x (full fp32)
    gemm_tf32_kernel<<<gD, blk, GEMM_SMEM_BYTES>>>(pAtt, pCW + CW_O, bo, x, nullptr, pRes1, MROWS, DD, DD, NORND);

    // 5. h2 = rmsnorm(res1) (tf32)
    rmsnorm_kernel<<<MROWS, 256>>>(pRes1, ln2w, pH2);

    // 6. gate = h2 @ w_gate (fp32)
    gemm_tf32_kernel<<<gI, blk, GEMM_SMEM_BYTES>>>(pH2, pCW + CW_G, nullptr, nullptr, nullptr, pGate, MROWS, II, DD, NORND);

    // 7. act = silu(gate) * (h2 @ w_up) (tf32)
    gemm_tf32_kernel<<<gI, blk, GEMM_SMEM_BYTES>>>(pH2, pCW + CW_U, nullptr, nullptr, pGate, pAct, MROWS, II, DD, RND);

    // 8. out = act @ w_down + res1
    gemm_tf32_kernel<<<gD, blk, GEMM_SMEM_BYTES>>>(pAct, pCW + CW_D, nullptr, pRes1, nullptr, out, MROWS, DD, II, NORND);
}